// round 16
// baseline (speedup 1.0000x reference)
#include <cuda_runtime.h>
#include <cstdint>

// ---------------------------------------------------------------------------
// Cluster-of-2 LSTM, feedback absorbed (W_eff = W_hh + W_ih⊗W_lin).
// 64 clusters x 2 CTAs x 256 threads; cluster owns 4 batches.
// Rank r owns units [64r, 64r+64) x ALL 4 gates -> W_eff rows for those units
// live ENTIRELY in registers (128 regs/thread); zero SMEM weight streaming.
// Per step: matvec(own-unit k) -> mbar wait (peer h) -> matvec(peer-unit k)
// -> xor1 fold -> local GX exchange -> update (local) -> h store local+DSMEM
// -> __syncthreads + t0 fence.acq_rel.cluster + remote mbarrier arrive.
// y partials -> GMEM ring -> tiny fold kernel.
// All cluster features used are sm_90 base (compute_103-safe); NO 'a' instrs.
// R15: fix missing `mbar` definition (R14 compile failure).
// ---------------------------------------------------------------------------

typedef unsigned long long ull;

#define THREADS 256
#define T_STEPS 2048

// SMEM float offsets
#define HB_B     148                   // batch stride (koff max 139)
#define HB_PAR   592                   // parity stride (4 batches)
#define GXO      1184                  // gate exchange: [4 batch][264]
#define GX_B     264
#define XBO      2240                  // 4 floats: step-0 x correction
#define MBAR_BYTE 8992                 // byte offset (8-aligned)
#define SMEM_BYTES 9216

__device__ float g_ypart[T_STEPS * 128 * 8];   // [step][cta][warp]

// ---- helpers ----------------------------------------------------------------
__device__ __forceinline__ ull pk2(float x, float y) {
    ull r; asm("mov.b64 %0, {%1, %2};" : "=l"(r) : "f"(x), "f"(y)); return r;
}
__device__ __forceinline__ float2 upk2(ull v) {
    float2 f; asm("mov.b64 {%0, %1}, %2;" : "=f"(f.x), "=f"(f.y) : "l"(v)); return f;
}
__device__ __forceinline__ ull ffma2(ull a, ull b, ull c) {
    ull d; asm("fma.rn.f32x2 %0, %1, %2, %3;" : "=l"(d) : "l"(a), "l"(b), "l"(c)); return d;
}
__device__ __forceinline__ float tanha(float x) {
    float y; asm("tanh.approx.f32 %0, %1;" : "=f"(y) : "f"(x)); return y;
}
__device__ __forceinline__ float siga(float x) { return fmaf(0.5f, tanha(0.5f * x), 0.5f); }

__device__ __forceinline__ uint32_t smem_u32(const void* p) {
    uint32_t a;
    asm("{ .reg .u64 t; cvta.to.shared.u64 t, %1; cvt.u32.u64 %0, t; }" : "=r"(a) : "l"(p));
    return a;
}
__device__ __forceinline__ uint32_t mapa_peer(uint32_t a, uint32_t rank) {
    uint32_t o;
    asm("mapa.shared::cluster.u32 %0, %1, %2;" : "=r"(o) : "r"(a), "r"(rank));
    return o;
}
__device__ __forceinline__ void st_remote_f32(uint32_t a, float v) {
    asm volatile("st.shared::cluster.b32 [%0], %1;" :: "r"(a), "r"(__float_as_uint(v)) : "memory");
}
#define MBAR_INIT(mb, c)  asm volatile("mbarrier.init.shared.b64 [%0], %1;" :: "r"(mb), "r"((uint32_t)(c)) : "memory")
#define MBAR_ARRIVE_REMOTE(ra) \
    asm volatile("mbarrier.arrive.release.cluster.shared::cluster.b64 _, [%0];" :: "r"(ra) : "memory")
#define FENCE_CLUSTER()   asm volatile("fence.acq_rel.cluster;" ::: "memory")
#define CLUSTER_SYNC() do { \
    asm volatile("barrier.cluster.arrive.aligned;" ::: "memory"); \
    asm volatile("barrier.cluster.wait.aligned;" ::: "memory"); \
} while (0)
#define MBAR_WAIT_CL(mb, ph) do {                                                \
    uint32_t _m = (mb), _p = (ph), _d;                                           \
    asm volatile("{\n\t.reg .pred p;\n\t"                                        \
        "mbarrier.try_wait.parity.acquire.cluster.shared::cta.b64 p, [%1], %2;\n\t" \
        "selp.b32 %0, 1, 0, p;\n\t}" : "=r"(_d) : "r"(_m), "r"(_p) : "memory");  \
    if (!_d) {                                                                   \
        asm volatile("{\n\t.reg .pred P1;\n\tWL_%=:\n\t"                         \
            "mbarrier.try_wait.parity.acquire.cluster.shared::cta.b64 P1, [%0], %1, 0x989680;\n\t" \
            "@P1 bra.uni WD_%=;\n\tbra.uni WL_%=;\n\tWD_%=:\n\t}"                \
            :: "r"(_m), "r"(_p) : "memory");                                     \
    }                                                                            \
} while (0)

// matvec over one k-section: weights WRI/WRF (16 ull each), h at hb + HOFF
#define MV_SEC(HOFF, WRI, WRF)                                                   \
    _Pragma("unroll")                                                            \
    for (int b = 0; b < 4; ++b) {                                                \
        const ulonglong2* H = (const ulonglong2*)(hb + b * HB_B + (HOFF));       \
        _Pragma("unroll")                                                        \
        for (int c = 0; c < 8; ++c) {                                            \
            ulonglong2 hv = H[c];                                                \
            ull wa = (WRI)[2 * c], wb_ = (WRI)[2 * c + 1];                       \
            ull wc = (WRF)[2 * c], wd_ = (WRF)[2 * c + 1];                       \
            aA[b] = ffma2(wa, hv.x, aA[b]); aA[b] = ffma2(wb_, hv.y, aA[b]);     \
            aB[b] = ffma2(wc, hv.x, aB[b]); aB[b] = ffma2(wd_, hv.y, aB[b]);     \
        }                                                                        \
    }

// One step. PARV: h read parity. DOWAIT: wait peer h (skip at step 0).
#define STEP_BODY(PARV, DOWAIT, ...)                                             \
    {                                                                            \
        const float* hb = sm + ((PARV) ? HB_PAR : 0);                            \
        ull aA[4] = {0, 0, 0, 0}, aB[4] = {0, 0, 0, 0};                          \
        MV_SEC(ownOff, wOA, wOB)                                                 \
        if (DOWAIT) MBAR_WAIT_CL(mbar, (PARV) ^ 1);                              \
        MV_SEC(peerOff, wPA, wPB)                                                \
        /* fold f32x2 + batch-pair xor1 */                                       \
        {                                                                        \
            float2 f;                                                            \
            f = upk2(aA[0]); float mA0 = f.x + f.y;                              \
            f = upk2(aA[1]); float mA1 = f.x + f.y;                              \
            f = upk2(aA[2]); float mA2 = f.x + f.y;                              \
            f = upk2(aA[3]); float mA3 = f.x + f.y;                              \
            f = upk2(aB[0]); float mB0 = f.x + f.y;                              \
            f = upk2(aB[1]); float mB1 = f.x + f.y;                              \
            f = upk2(aB[2]); float mB2 = f.x + f.y;                              \
            f = upk2(aB[3]); float mB3 = f.x + f.y;                              \
            float vA01 = (ks ? mA1 : mA0) + __shfl_xor_sync(~0u, ks ? mA0 : mA1, 1); \
            float vB01 = (ks ? mB1 : mB0) + __shfl_xor_sync(~0u, ks ? mB0 : mB1, 1); \
            float vA23 = (ks ? mA3 : mA2) + __shfl_xor_sync(~0u, ks ? mA2 : mA3, 1); \
            float vB23 = (ks ? mB3 : mB2) + __shfl_xor_sync(~0u, ks ? mB2 : mB3, 1); \
            sm[gxw]       = vA01; sm[gxw + 64]       = vB01;                     \
            sm[gxw + 528] = vA23; sm[gxw + 528 + 64] = vB23;                     \
        }                                                                        \
        __syncthreads();                                                         \
        /* update (unit uG2, batch ub) -- fully local */                         \
        {                                                                        \
            const float* gx = sm + GXO + ub * GX_B + uu;                         \
            float gI = gx[0]   + biasu[0];                                       \
            float gF = gx[64]  + biasu[1];                                       \
            float gG = gx[128] + biasu[2];                                       \
            float gO = gx[192] + biasu[3];                                       \
            __VA_ARGS__                                                          \
            float iv = siga(gI), fv = siga(gF), gv = tanha(gG), ov = siga(gO);   \
            c_state = fv * c_state + iv * gv;                                    \
            float hn = ov * tanha(c_state);                                      \
            int ho = ((PARV) ? 0 : HB_PAR) + hoff0;   /* write parity P^1 */     \
            sm[ho] = hn;                                                         \
            st_remote_f32(rSB + 4u * (uint32_t)ho, hn);                          \
            float py = hn * wlinu;                                               \
            py += __shfl_xor_sync(~0u, py, 1);                                   \
            py += __shfl_xor_sync(~0u, py, 2);                                   \
            py += __shfl_xor_sync(~0u, py, 4);                                   \
            py += __shfl_xor_sync(~0u, py, 8);                                   \
            py += __shfl_xor_sync(~0u, py, 16);                                  \
            if (lane == 0) g_ypart[(step * 128 + ctaIdx) * 8 + w] = py;          \
        }                                                                        \
        __syncthreads();                                                         \
        if (t == 0) { FENCE_CLUSTER(); MBAR_ARRIVE_REMOTE(rSB + MBAR_BYTE); }    \
    }

__global__ void __launch_bounds__(THREADS, 1) __cluster_dims__(2, 1, 1)
lstm_cl_kernel(const int*   __restrict__ label,
               const float* __restrict__ h0,
               const float* __restrict__ W_ih,
               const float* __restrict__ W_hh,
               const float* __restrict__ b_ih,
               const float* __restrict__ b_hh,
               const float* __restrict__ W_lin,
               const float* __restrict__ b_lin)
{
    extern __shared__ float sm[];
    const uint32_t sb = smem_u32(sm);
    const uint32_t mbar = sb + MBAR_BYTE;          // R15 fix: was undefined
    const int t = threadIdx.x;
    const int ctaIdx = blockIdx.x;
    const int clu = ctaIdx >> 1;
    uint32_t rank;
    asm("mov.u32 %0, %%cluster_ctarank;" : "=r"(rank));
    const int p = t >> 1, ks = t & 1;
    const int lane = t & 31, w = t >> 5;
    const float blin = b_lin[0];

    // ---- init ----------------------------------------------------------------
    // h_init -> parity 0, all 4 batches, full 128 units (local copy)
    for (int idx = t; idx < 4 * 128; idx += THREADS) {
        int b = idx >> 7, u = idx & 127;
        int lab = label[4 * clu + b];
        sm[b * HB_B + (u >> 5) * 36 + (u & 31)] = h0[lab * 128 + u];
    }
    // xb0 per batch (warps 0-3): -(W_lin . h_init_b + blin)
    if (w < 4) {
        int lab = label[4 * clu + w];
        float a = 0.0f;
#pragma unroll
        for (int q = 0; q < 4; ++q) {
            int u = lane + 32 * q;
            a = fmaf(W_lin[u], h0[lab * 128 + u], a);
        }
#pragma unroll
        for (int off = 16; off; off >>= 1) a += __shfl_xor_sync(~0u, a, off);
        if (lane == 0) sm[XBO + w] = -(a + blin);
    }
    if (t == 0) MBAR_INIT(mbar, 1);

    // Register weights: unit uT = 64*rank + (p&63); rows (gA,gB):
    // p<64 -> gates (i,f); p>=64 -> gates (g,o). k: section x (32*ks + [0,32)).
    // wO* = own section (k in my units), wP* = peer section.
    ull wOA[16], wOB[16], wPA[16], wPB[16];
    {
        const int uT = 64 * (int)rank + (p & 63);
        const int gA = (p < 64) ? 0 : 2;
        const int rowA = gA * 128 + uT, rowB = rowA + 128;
        const float wihA = W_ih[rowA], wihB = W_ih[rowB];
#pragma unroll
        for (int si = 0; si < 2; ++si) {
            int sec = (int)rank ^ si;
            int kb = sec * 64 + ks * 32;
            ull* dA = si ? wPA : wOA;
            ull* dB = si ? wPB : wOB;
#pragma unroll
            for (int c = 0; c < 16; ++c) {
                int k0 = kb + 2 * c, k1 = k0 + 1;
                float a0 = W_hh[rowA * 128 + k0] + wihA * W_lin[k0];
                float a1 = W_hh[rowA * 128 + k1] + wihA * W_lin[k1];
                float b0 = W_hh[rowB * 128 + k0] + wihB * W_lin[k0];
                float b1 = W_hh[rowB * 128 + k1] + wihB * W_lin[k1];
                dA[c] = pk2(a0, a1);
                dB[c] = pk2(b0, b1);
            }
        }
    }

    // matvec constants
    const int ownOff  = (2 * (int)rank + ks) * 36;
    const int peerOff = (2 * ((int)rank ^ 1) + ks) * 36;
    const int gxw = GXO + ks * GX_B + ((p < 64) ? 0 : 128) + (p & 63);

    // updater constants: unit uG2 = 64*rank + (t&63), batch ub = t>>6
    const int uu = t & 63;
    const int ub = t >> 6;
    const int uG2 = 64 * (int)rank + uu;
    float biasu[4];
#pragma unroll
    for (int q = 0; q < 4; ++q)
        biasu[q] = b_ih[q * 128 + uG2] + b_hh[q * 128 + uG2] + W_ih[q * 128 + uG2] * blin;
    const float wlinu = W_lin[uG2];
    const int hoff0 = ub * HB_B + (uG2 >> 5) * 36 + (uG2 & 31);
    float c_state = 0.0f;

    const uint32_t rSB = mapa_peer(sb, rank ^ 1u);   // peer SMEM base

    __syncthreads();
    CLUSTER_SYNC();   // mbar init + h_init visible cluster-wide

    int step = 0;

    // ---- step 0: no wait; one-time x0 correction -------------------------------
    STEP_BODY(0, false,
              { float xb = sm[XBO + ub];
                gI += xb * W_ih[uG2];
                gF += xb * W_ih[128 + uG2];
                gG += xb * W_ih[256 + uG2];
                gO += xb * W_ih[384 + uG2]; })
    ++step;

    // ---- steps 1..2046 ----------------------------------------------------------
#pragma unroll 1
    for (int it = 0; it < (T_STEPS - 2) / 2; ++it) {
        STEP_BODY(1, true, ;)
        ++step;
        STEP_BODY(0, true, ;)
        ++step;
    }
    // ---- step 2047 ---------------------------------------------------------------
    STEP_BODY(1, true, ;)

    CLUSTER_SYNC();   // no CTA exits while peer DSMEM ops may be in flight
}

// out[s, 4*clu + b] = sum over 2 CTAs x 2 warps of ring partials + b_lin
__global__ void y_fold_kernel(float* __restrict__ out,
                              const float* __restrict__ b_lin)
{
    const int s = blockIdx.x;
    const int i = threadIdx.x;           // i = 4*clu + b
    const int clu = i >> 2, b = i & 3;
    const float* r0 = g_ypart + (s * 128 + 2 * clu) * 8;
    const float* r1 = r0 + 8;
    out[s * 256 + i] = (r0[2 * b] + r0[2 * b + 1])
                     + (r1[2 * b] + r1[2 * b + 1]) + b_lin[0];
}

extern "C" void kernel_launch(void* const* d_in, const int* in_sizes, int n_in,
                              void* d_out, int out_size) {
    // metadata order: input, label, h0, W_ih, W_hh, b_ih, b_hh, W_lin, b_lin
    const int*   label  = (const int*)  d_in[1];
    const float* h0     = (const float*)d_in[2];
    const float* W_ih   = (const float*)d_in[3];
    const float* W_hh   = (const float*)d_in[4];
    const float* b_ih   = (const float*)d_in[5];
    const float* b_hh   = (const float*)d_in[6];
    const float* W_lin  = (const float*)d_in[7];
    const float* b_lin  = (const float*)d_in[8];
    float* out = (float*)d_out;

    lstm_cl_kernel<<<128, THREADS, SMEM_BYTES>>>(label, h0, W_ih, W_hh,
                                                 b_ih, b_hh, W_lin, b_lin);
    y_fold_kernel<<<T_STEPS, 256>>>(out, b_lin);
}